// round 12
// baseline (speedup 1.0000x reference)
#include <cuda_runtime.h>
#include <cuda_bf16.h>

// Problem: DotProductAttention_83476984365340
// softmax over singleton axis == 1.0 -> output = values.sum(axis=1).
// Pure HBM-bound column sum of values [32, 4096, 1024] f32 (512 MiB read).
//
// Grid swept -> 256 CTAs (1.7/SM, 2MiB aligned stream/CTA) optimal.
// Pipeline-depth sweep (double-buffered, issue-next-before-consume):
//   pipe8:  80 regs, 6.96 TB/s, ncu 77.7us
//   pipe10: 102 regs, 7.10 TB/s, ncu 76.2us, DRAM 89.6%  <- champion
//   pipe12: 128 regs (CAP -> spill-compromised), 6.77 TB/s
// R12: PIPE=11 (~112 regs predicted, under cap). 512 = 46*11 + 6 tail.

#define B_DIM 32
#define T_DIM 4096
#define D_DIM 1024
#define CHUNKS_PER_B 8
#define T_PER_CHUNK (T_DIM / CHUNKS_PER_B)  // 512 rows = 2 MiB per CTA
#define THREADS 256                          // 256 threads * float4 = 1024 = D
#define PIPE 11                              // double-buffer depth
#define FULLG (T_PER_CHUNK / PIPE)           // 46 full groups
#define TAIL (T_PER_CHUNK - FULLG * PIPE)    // 6

__global__ __launch_bounds__(THREADS, 2)
void values_colsum_kernel(const float* __restrict__ values, float* __restrict__ out)
{
    const int b  = blockIdx.y;                 // 0..31
    const int c  = blockIdx.x;                 // 0..7
    const int d4 = threadIdx.x;                // float4 lane within row (0..255)

    const float4* __restrict__ p =
        reinterpret_cast<const float4*>(values) +
        (size_t)b * T_DIM * (D_DIM / 4) +
        (size_t)c * T_PER_CHUNK * (D_DIM / 4) +
        d4;

    float4 acc0 = make_float4(0.f, 0.f, 0.f, 0.f);
    float4 acc1 = make_float4(0.f, 0.f, 0.f, 0.f);

    // Prologue: fill buffer A.
    float4 va[PIPE], vb[PIPE];
    #pragma unroll
    for (int k = 0; k < PIPE; ++k)
        va[k] = p[(size_t)k * (D_DIM / 4)];
    p += (size_t)PIPE * (D_DIM / 4);

    // Steady state: FULLG-1 = 45 iterations of issue-next-then-consume.
    for (int it = 0; it < FULLG - 1; ++it) {
        float4* cur  = (it & 1) ? vb : va;
        float4* next = (it & 1) ? va : vb;

        #pragma unroll
        for (int k = 0; k < PIPE; ++k)
            next[k] = p[(size_t)k * (D_DIM / 4)];
        p += (size_t)PIPE * (D_DIM / 4);

        #pragma unroll
        for (int k = 0; k < PIPE - 1; k += 2) {
            acc0.x += cur[k].x;   acc0.y += cur[k].y;
            acc0.z += cur[k].z;   acc0.w += cur[k].w;
            acc1.x += cur[k+1].x; acc1.y += cur[k+1].y;
            acc1.z += cur[k+1].z; acc1.w += cur[k+1].w;
        }
        // Odd element (PIPE=11).
        acc0.x += cur[PIPE-1].x; acc0.y += cur[PIPE-1].y;
        acc0.z += cur[PIPE-1].z; acc0.w += cur[PIPE-1].w;
    }

    // Epilogue: drain last full group while issuing the 6-row tail, then tail.
    // (FULLG-1 = 45 odd -> last filled buffer is vb.)
    {
        float4* cur = ((FULLG - 1) & 1) ? vb : va;
        float4 vt[TAIL];

        #pragma unroll
        for (int k = 0; k < TAIL; ++k)
            vt[k] = p[(size_t)k * (D_DIM / 4)];

        #pragma unroll
        for (int k = 0; k < PIPE - 1; k += 2) {
            acc0.x += cur[k].x;   acc0.y += cur[k].y;
            acc0.z += cur[k].z;   acc0.w += cur[k].w;
            acc1.x += cur[k+1].x; acc1.y += cur[k+1].y;
            acc1.z += cur[k+1].z; acc1.w += cur[k+1].w;
        }
        acc0.x += cur[PIPE-1].x; acc0.y += cur[PIPE-1].y;
        acc0.z += cur[PIPE-1].z; acc0.w += cur[PIPE-1].w;

        #pragma unroll
        for (int k = 0; k < TAIL; k += 2) {
            acc0.x += vt[k].x;   acc0.y += vt[k].y;
            acc0.z += vt[k].z;   acc0.w += vt[k].w;
            acc1.x += vt[k+1].x; acc1.y += vt[k+1].y;
            acc1.z += vt[k+1].z; acc1.w += vt[k+1].w;
        }
    }

    acc0.x += acc1.x; acc0.y += acc1.y; acc0.z += acc1.z; acc0.w += acc1.w;

    float* o = out + (size_t)b * D_DIM + d4 * 4;
    atomicAdd(o + 0, acc0.x);
    atomicAdd(o + 1, acc0.y);
    atomicAdd(o + 2, acc0.z);
    atomicAdd(o + 3, acc0.w);
}

extern "C" void kernel_launch(void* const* d_in, const int* in_sizes, int n_in,
                              void* d_out, int out_size)
{
    // Input order per reference setup_inputs(): query, keys, values, W
    const float* values = (const float*)d_in[2];
    float* out = (float*)d_out;

    cudaMemsetAsync(out, 0, (size_t)out_size * sizeof(float));

    dim3 grid(CHUNKS_PER_B, B_DIM);
    values_colsum_kernel<<<grid, THREADS>>>(values, out);
}

// round 13
// speedup vs baseline: 1.0127x; 1.0127x over previous
#include <cuda_runtime.h>
#include <cuda_bf16.h>

// Problem: DotProductAttention_83476984365340
// softmax over singleton axis == 1.0 -> output = values.sum(axis=1).
// Pure HBM-bound column sum of values [32, 4096, 1024] f32 (512 MiB read).
//
// FINAL configuration — all axes swept and bracketed:
//   grid: 256 CTAs = 8 chunks x 32 batches (1.7/SM, 2MiB aligned stream/CTA)
//     [148: 6.39 | 256: 7.10 | 296: 6.67 | 512: 6.61 | 1024: 6.38 TB/s]
//   pipeline depth (double-buffered, issue-next-before-consume):
//     [8: 6.96 | 10: 7.10 <- best | 11: 6.77 | 12: 6.77 TB/s]
//     depth>10 regresses even with reg slack: odd 44KB groups break the
//     aligned 40KB group cadence and ptxas's load batching.
//   caching: default (evict-first .cs regressed)
// Champion: ncu 76.2us, 7.10 TB/s, DRAM 89.6% — at the HBM3e streaming wall.

#define B_DIM 32
#define T_DIM 4096
#define D_DIM 1024
#define CHUNKS_PER_B 8
#define T_PER_CHUNK (T_DIM / CHUNKS_PER_B)  // 512 rows = 2 MiB per CTA
#define THREADS 256                          // 256 threads * float4 = 1024 = D
#define PIPE 10                              // double-buffer depth
#define FULLG (T_PER_CHUNK / PIPE)           // 51 -> use 50 full + tail
#define FULLG_USED 50
#define TAIL (T_PER_CHUNK - FULLG_USED * PIPE)  // 12

__global__ __launch_bounds__(THREADS, 2)
void values_colsum_kernel(const float* __restrict__ values, float* __restrict__ out)
{
    const int b  = blockIdx.y;                 // 0..31
    const int c  = blockIdx.x;                 // 0..7
    const int d4 = threadIdx.x;                // float4 lane within row (0..255)

    const float4* __restrict__ p =
        reinterpret_cast<const float4*>(values) +
        (size_t)b * T_DIM * (D_DIM / 4) +
        (size_t)c * T_PER_CHUNK * (D_DIM / 4) +
        d4;

    float4 acc0 = make_float4(0.f, 0.f, 0.f, 0.f);
    float4 acc1 = make_float4(0.f, 0.f, 0.f, 0.f);

    // Prologue: fill buffer A.
    float4 va[PIPE], vb[PIPE];
    #pragma unroll
    for (int k = 0; k < PIPE; ++k)
        va[k] = p[(size_t)k * (D_DIM / 4)];
    p += (size_t)PIPE * (D_DIM / 4);

    // Steady state: FULLG_USED-1 = 49 iterations of issue-next-then-consume.
    for (int it = 0; it < FULLG_USED - 1; ++it) {
        float4* cur  = (it & 1) ? vb : va;
        float4* next = (it & 1) ? va : vb;

        #pragma unroll
        for (int k = 0; k < PIPE; ++k)
            next[k] = p[(size_t)k * (D_DIM / 4)];
        p += (size_t)PIPE * (D_DIM / 4);

        #pragma unroll
        for (int k = 0; k < PIPE; k += 2) {
            acc0.x += cur[k].x;   acc0.y += cur[k].y;
            acc0.z += cur[k].z;   acc0.w += cur[k].w;
            acc1.x += cur[k+1].x; acc1.y += cur[k+1].y;
            acc1.z += cur[k+1].z; acc1.w += cur[k+1].w;
        }
    }

    // Epilogue: drain last full group while issuing the 12-row tail,
    // then drain the tail. (FULLG_USED-1 = 49 odd -> last filled is vb.)
    {
        float4* cur = ((FULLG_USED - 1) & 1) ? vb : va;
        float4 vt[TAIL];

        #pragma unroll
        for (int k = 0; k < TAIL; ++k)
            vt[k] = p[(size_t)k * (D_DIM / 4)];

        #pragma unroll
        for (int k = 0; k < PIPE; k += 2) {
            acc0.x += cur[k].x;   acc0.y += cur[k].y;
            acc0.z += cur[k].z;   acc0.w += cur[k].w;
            acc1.x += cur[k+1].x; acc1.y += cur[k+1].y;
            acc1.z += cur[k+1].z; acc1.w += cur[k+1].w;
        }

        #pragma unroll
        for (int k = 0; k < TAIL; k += 2) {
            acc0.x += vt[k].x;   acc0.y += vt[k].y;
            acc0.z += vt[k].z;   acc0.w += vt[k].w;
            acc1.x += vt[k+1].x; acc1.y += vt[k+1].y;
            acc1.z += vt[k+1].z; acc1.w += vt[k+1].w;
        }
    }

    acc0.x += acc1.x; acc0.y += acc1.y; acc0.z += acc1.z; acc0.w += acc1.w;

    float* o = out + (size_t)b * D_DIM + d4 * 4;
    atomicAdd(o + 0, acc0.x);
    atomicAdd(o + 1, acc0.y);
    atomicAdd(o + 2, acc0.z);
    atomicAdd(o + 3, acc0.w);
}

extern "C" void kernel_launch(void* const* d_in, const int* in_sizes, int n_in,
                              void* d_out, int out_size)
{
    // Input order per reference setup_inputs(): query, keys, values, W
    const float* values = (const float*)d_in[2];
    float* out = (float*)d_out;

    cudaMemsetAsync(out, 0, (size_t)out_size * sizeof(float));

    dim3 grid(CHUNKS_PER_B, B_DIM);
    values_colsum_kernel<<<grid, THREADS>>>(values, out);
}

// round 14
// speedup vs baseline: 1.0341x; 1.0211x over previous
#include <cuda_runtime.h>
#include <cuda_bf16.h>

// Problem: DotProductAttention_83476984365340
// softmax over singleton axis == 1.0 -> output = values.sum(axis=1).
// Pure HBM-bound column sum of values [32, 4096, 1024] f32 (512 MiB read).
//
// Grid: 256 CTAs optimal (swept 148..1184). Depth sweep (ncu TB/s):
//   8: 6.96 | 10: 7.10 / 6.96 (2 runs) | 11: 6.77 | 12: 6.77
// ncu noise band: +/-1.5us. R14 = last untested interior point, PIPE=9:
// tests the even-depth/symmetric-consume hypothesis for the >10 falloff.
// 512 rows = 56 groups of 9 + 8-row tail. ~94 regs.

#define B_DIM 32
#define T_DIM 4096
#define D_DIM 1024
#define CHUNKS_PER_B 8
#define T_PER_CHUNK (T_DIM / CHUNKS_PER_B)  // 512 rows = 2 MiB per CTA
#define THREADS 256                          // 256 threads * float4 = 1024 = D
#define PIPE 9                               // double-buffer depth
#define FULLG_USED (T_PER_CHUNK / PIPE)      // 56 full groups
#define TAIL (T_PER_CHUNK - FULLG_USED * PIPE)  // 8

__global__ __launch_bounds__(THREADS, 2)
void values_colsum_kernel(const float* __restrict__ values, float* __restrict__ out)
{
    const int b  = blockIdx.y;                 // 0..31
    const int c  = blockIdx.x;                 // 0..7
    const int d4 = threadIdx.x;                // float4 lane within row (0..255)

    const float4* __restrict__ p =
        reinterpret_cast<const float4*>(values) +
        (size_t)b * T_DIM * (D_DIM / 4) +
        (size_t)c * T_PER_CHUNK * (D_DIM / 4) +
        d4;

    float4 acc0 = make_float4(0.f, 0.f, 0.f, 0.f);
    float4 acc1 = make_float4(0.f, 0.f, 0.f, 0.f);

    // Prologue: fill buffer A.
    float4 va[PIPE], vb[PIPE];
    #pragma unroll
    for (int k = 0; k < PIPE; ++k)
        va[k] = p[(size_t)k * (D_DIM / 4)];
    p += (size_t)PIPE * (D_DIM / 4);

    // Steady state: FULLG_USED-1 = 55 iterations of issue-next-then-consume.
    for (int it = 0; it < FULLG_USED - 1; ++it) {
        float4* cur  = (it & 1) ? vb : va;
        float4* next = (it & 1) ? va : vb;

        #pragma unroll
        for (int k = 0; k < PIPE; ++k)
            next[k] = p[(size_t)k * (D_DIM / 4)];
        p += (size_t)PIPE * (D_DIM / 4);

        #pragma unroll
        for (int k = 0; k < PIPE - 1; k += 2) {
            acc0.x += cur[k].x;   acc0.y += cur[k].y;
            acc0.z += cur[k].z;   acc0.w += cur[k].w;
            acc1.x += cur[k+1].x; acc1.y += cur[k+1].y;
            acc1.z += cur[k+1].z; acc1.w += cur[k+1].w;
        }
        // Odd element (PIPE=9).
        acc0.x += cur[PIPE-1].x; acc0.y += cur[PIPE-1].y;
        acc0.z += cur[PIPE-1].z; acc0.w += cur[PIPE-1].w;
    }

    // Epilogue: drain last full group while issuing the 8-row tail, then tail.
    // (FULLG_USED-1 = 55 odd -> last filled buffer is vb.)
    {
        float4* cur = ((FULLG_USED - 1) & 1) ? vb : va;
        float4 vt[TAIL];

        #pragma unroll
        for (int k = 0; k < TAIL; ++k)
            vt[k] = p[(size_t)k * (D_DIM / 4)];

        #pragma unroll
        for (int k = 0; k < PIPE - 1; k += 2) {
            acc0.x += cur[k].x;   acc0.y += cur[k].y;
            acc0.z += cur[k].z;   acc0.w += cur[k].w;
            acc1.x += cur[k+1].x; acc1.y += cur[k+1].y;
            acc1.z += cur[k+1].z; acc1.w += cur[k+1].w;
        }
        acc0.x += cur[PIPE-1].x; acc0.y += cur[PIPE-1].y;
        acc0.z += cur[PIPE-1].z; acc0.w += cur[PIPE-1].w;

        #pragma unroll
        for (int k = 0; k < TAIL; k += 2) {
            acc0.x += vt[k].x;   acc0.y += vt[k].y;
            acc0.z += vt[k].z;   acc0.w += vt[k].w;
            acc1.x += vt[k+1].x; acc1.y += vt[k+1].y;
            acc1.z += vt[k+1].z; acc1.w += vt[k+1].w;
        }
    }

    acc0.x += acc1.x; acc0.y += acc1.y; acc0.z += acc1.z; acc0.w += acc1.w;

    float* o = out + (size_t)b * D_DIM + d4 * 4;
    atomicAdd(o + 0, acc0.x);
    atomicAdd(o + 1, acc0.y);
    atomicAdd(o + 2, acc0.z);
    atomicAdd(o + 3, acc0.w);
}

extern "C" void kernel_launch(void* const* d_in, const int* in_sizes, int n_in,
                              void* d_out, int out_size)
{
    // Input order per reference setup_inputs(): query, keys, values, W
    const float* values = (const float*)d_in[2];
    float* out = (float*)d_out;

    cudaMemsetAsync(out, 0, (size_t)out_size * sizeof(float));

    dim3 grid(CHUNKS_PER_B, B_DIM);
    values_colsum_kernel<<<grid, THREADS>>>(values, out);
}